// round 15
// baseline (speedup 1.0000x reference)
#include <cuda_runtime.h>
#include <cuda_bf16.h>
#include <math.h>
#include <stdint.h>

// Problem constants
#define B_ 128
#define T_ 512
#define I_ 256
#define H_ 1024
#define O_ 256

#define NB   128      // persistent grid: 4 M-tiles x 32 N-tiles
#define NTHR 256      // 8 warps: warps 0-3 = stream 0 (even chunks), 4-7 = stream 1

// ---------------------------------------------------------------------------
// Device-global scratch (allocation-free per harness rules)
// int8 plane representation: v ~ (p1*128 + p0) / scale, p0 in [-64,63]
//   x: scale 2^11, h: scale 2^14, W (both): scale 2^18
// ---------------------------------------------------------------------------
__device__ char g_x1[(size_t)B_ * T_ * I_];
__device__ char g_x0[(size_t)B_ * T_ * I_];
__device__ char g_h1[2][B_ * H_];
__device__ char g_h0[2][B_ * H_];
__device__ float g_h32[B_ * H_];
__device__ unsigned g_bar_count4[128];
__device__ unsigned g_bar_phase4[128];

// ---------------------------------------------------------------------------
// SMEM layout
// ---------------------------------------------------------------------------
#define SM_W1     0            // W_hh plane1: 32 rows x 1024B, swizzled
#define SM_W0     32768        // W_hh plane0
#define SM_WI1    65536        // W_ih plane1: 32 rows x 256B
#define SM_WI0    73728
#define SM_ASTAGE 81920        // 2 streams x 2 stages x 8192B (plane1 4K + plane0 4K)
#define SM_RED    (81920 + 16384)   // alias stream1 stage0 (safe in epilogue)
#define SM_BIAS   114688       // 32 floats
#define SM_TOTAL  114816

// ---------------------------------------------------------------------------
// PTX helpers (portable ISA for plain sm_103 target — NO tcgen05)
// ---------------------------------------------------------------------------
__device__ __forceinline__ uint32_t smem_u32(const void* p) {
    uint32_t a;
    asm("{ .reg .u64 t; cvta.to.shared.u64 t, %1; cvt.u32.u64 %0, t; }" : "=r"(a) : "l"(p));
    return a;
}

__device__ __forceinline__ void cp16(uint32_t saddr, const void* gptr) {
    asm volatile("cp.async.cg.shared.global [%0], [%1], 16;"
                 :: "r"(saddr), "l"(__cvta_generic_to_global(gptr)));
}

__device__ __forceinline__ void ldsm_x4(uint32_t* r, uint32_t addr) {
    asm volatile("ldmatrix.sync.aligned.m8n8.x4.shared.b16 {%0,%1,%2,%3}, [%4];"
                 : "=r"(r[0]), "=r"(r[1]), "=r"(r[2]), "=r"(r[3]) : "r"(addr));
}

// s8 IMMA k32 — byte-layout isomorphic to bf16 HMMA k16 fragments
__device__ __forceinline__ void imma16832(int* c, const uint32_t* a, uint32_t b0, uint32_t b1) {
    asm volatile(
        "mma.sync.aligned.m16n8k32.row.col.s32.s8.s8.s32 "
        "{%0,%1,%2,%3}, {%4,%5,%6,%7}, {%8,%9}, {%0,%1,%2,%3};"
        : "+r"(c[0]), "+r"(c[1]), "+r"(c[2]), "+r"(c[3])
        : "r"(a[0]), "r"(a[1]), "r"(a[2]), "r"(a[3]), "r"(b0), "r"(b1));
}

__device__ __forceinline__ void stream_bar(int stream) {
    asm volatile("bar.sync %0, 128;" :: "r"(1 + stream) : "memory");
}

// Group-local sense-reversing barrier: 32 CTAs sharing a batch group (ctaM)
__device__ __forceinline__ void group_barrier(int grp, unsigned* phase) {
    __syncthreads();
    if (threadIdx.x == 0) {
        unsigned target = *phase + 1;
        unsigned* cnt = &g_bar_count4[grp * 32];
        unsigned* ph  = &g_bar_phase4[grp * 32];
        if (atomicAdd(cnt, 1) == 31) {
            *cnt = 0;
            __threadfence();
            atomicExch(ph, target);
        } else {
            while (((volatile unsigned*)ph)[0] != target) {}
            __threadfence();
        }
        *phase = target;
    }
    __syncthreads();
}

// ---------------------------------------------------------------------------
// Prep kernels: int8 plane splits of x and initial hidden
// ---------------------------------------------------------------------------
__global__ void split_x_int8(const float* __restrict__ x)
{
    int i = blockIdx.x * blockDim.x + threadIdx.x;
    if (i < B_ * T_ * I_) {
        int X = __float2int_rn(x[i] * 2048.f);       // scale 2^11
        X = max(min(X, 16319), -16320);
        int p1 = (X + 64) >> 7;
        g_x1[i] = (char)p1;
        g_x0[i] = (char)(X - (p1 << 7));
    }
}

__global__ void init_h_int8(const float* __restrict__ hidden)
{
    int i = blockIdx.x * blockDim.x + threadIdx.x;
    if (i < B_ * H_) {
        int Hq = __float2int_rn(hidden[i] * 16384.f);  // scale 2^14
        Hq = max(min(Hq, 16319), -16320);
        int p1 = (Hq + 64) >> 7;
        g_h1[0][i] = (char)p1;
        g_h0[0][i] = (char)(Hq - (p1 << 7));
    }
}

// ---------------------------------------------------------------------------
// Stream-local chunk loader: 128 threads load 8KB (plane1 4KB + plane0 4KB).
// Rows 128B, swizzle (col16B) ^ ((row&7)*16). c<8: h chunk; c>=8: x chunk.
// ---------------------------------------------------------------------------
__device__ __forceinline__ void load_chunk(uint32_t sstage, int c,
    const char* __restrict__ h1p, const char* __restrict__ h0p,
    int m0, int t, int stid)
{
    if (c < 8) {
        #pragma unroll
        for (int i = 0; i < 2; i++) {
            int u = stid + i * 128;
            int row = u >> 3, uk = u & 7;
            int so = row * 128 + ((uk * 16) ^ ((row & 7) * 16));
            size_t go = (size_t)(m0 + row) * 1024 + (size_t)c * 128 + uk * 16;
            cp16(sstage + so, h1p + go);
            cp16(sstage + 4096 + so, h0p + go);
        }
    } else {
        int cx = c - 8;
        #pragma unroll
        for (int i = 0; i < 2; i++) {
            int u = stid + i * 128;
            int row = u >> 3, uk = u & 7;
            int so = row * 128 + ((uk * 16) ^ ((row & 7) * 16));
            size_t go = ((size_t)(m0 + row) * T_ + t) * 256 + cx * 128 + uk * 16;
            cp16(sstage + so, g_x1 + go);
            cp16(sstage + 4096 + so, g_x0 + go);
        }
    }
}

// ---------------------------------------------------------------------------
// Persistent recurrence: 512 steps, one launch. Int16-fixed-point via IMMA.
// CTA (ctaM, ctaN): M-tile 32 batches, N-tile 32 cols, K = 1024(h)+256(x).
// Dual K-parity streams of 4 warps (M16xN16); chunks k128 (4 kk32 each).
// Per kk32: 3 IMMA per n8-tile (h1w1 -> hi; h1w0, h0w1 -> mid; h0w0 dropped).
// ---------------------------------------------------------------------------
__global__ __launch_bounds__(NTHR, 1) void rnn_persistent(
    const float* __restrict__ b_ih, const float* __restrict__ b_hh,
    const float* __restrict__ Whh, const float* __restrict__ Wih)
{
    extern __shared__ char sm[];
    const uint32_t smb = smem_u32(sm);
    const int tid = threadIdx.x;
    const int lid = tid & 31;
    const int wid = tid >> 5;
    const int stream = wid >> 2;
    const int stid = tid & 127;
    const int swid = wid & 3;
    const int wm = swid >> 1, wn = swid & 1;
    const int ctaM = blockIdx.x >> 5;
    const int ctaN = blockIdx.x & 31;
    const int m0 = ctaM * 32;
    const int n0 = ctaN * 32;

    // ---- Prologue: split W slices fp32 -> int8 planes directly into smem ----
    {
        // W_hh slice: 32 rows x 1024 -> 8192 float4 units
        for (int u = tid; u < 8192; u += NTHR) {
            int row = u >> 8, k4 = u & 255;
            float4 v = *(const float4*)(Whh + (size_t)(n0 + row) * H_ + k4 * 4);
            int w0i = __float2int_rn(v.x * 262144.f);   // scale 2^18, |W'|<=8192
            int w1i = __float2int_rn(v.y * 262144.f);
            int w2i = __float2int_rn(v.z * 262144.f);
            int w3i = __float2int_rn(v.w * 262144.f);
            int a0 = (w0i + 64) >> 7, a1 = (w1i + 64) >> 7,
                a2 = (w2i + 64) >> 7, a3 = (w3i + 64) >> 7;
            uint32_t hi = (uint32_t)(a0 & 0xFF) | ((uint32_t)(a1 & 0xFF) << 8) |
                          ((uint32_t)(a2 & 0xFF) << 16) | ((uint32_t)(a3 & 0xFF) << 24);
            int b0 = w0i - (a0 << 7), b1 = w1i - (a1 << 7),
                b2 = w2i - (a2 << 7), b3 = w3i - (a3 << 7);
            uint32_t lo = (uint32_t)(b0 & 0xFF) | ((uint32_t)(b1 & 0xFF) << 8) |
                          ((uint32_t)(b2 & 0xFF) << 16) | ((uint32_t)(b3 & 0xFF) << 24);
            int so = row * 1024 + ((k4 * 4) ^ ((row & 7) * 16));
            *(uint32_t*)(sm + SM_W1 + so) = hi;
            *(uint32_t*)(sm + SM_W0 + so) = lo;
        }
        // W_ih slice: 32 rows x 256 -> 2048 float4 units
        for (int u = tid; u < 2048; u += NTHR) {
            int row = u >> 6, k4 = u & 63;
            float4 v = *(const float4*)(Wih + (size_t)(n0 + row) * I_ + k4 * 4);
            int w0i = __float2int_rn(v.x * 262144.f);
            int w1i = __float2int_rn(v.y * 262144.f);
            int w2i = __float2int_rn(v.z * 262144.f);
            int w3i = __float2int_rn(v.w * 262144.f);
            int a0 = (w0i + 64) >> 7, a1 = (w1i + 64) >> 7,
                a2 = (w2i + 64) >> 7, a3 = (w3i + 64) >> 7;
            uint32_t hi = (uint32_t)(a0 & 0xFF) | ((uint32_t)(a1 & 0xFF) << 8) |
                          ((uint32_t)(a2 & 0xFF) << 16) | ((uint32_t)(a3 & 0xFF) << 24);
            int b0 = w0i - (a0 << 7), b1 = w1i - (a1 << 7),
                b2 = w2i - (a2 << 7), b3 = w3i - (a3 << 7);
            uint32_t lo = (uint32_t)(b0 & 0xFF) | ((uint32_t)(b1 & 0xFF) << 8) |
                          ((uint32_t)(b2 & 0xFF) << 16) | ((uint32_t)(b3 & 0xFF) << 24);
            int so = row * 256 + ((k4 * 4) ^ ((row & 7) * 16));
            *(uint32_t*)(sm + SM_WI1 + so) = hi;
            *(uint32_t*)(sm + SM_WI0 + so) = lo;
        }
        if (tid < 32)
            ((float*)(sm + SM_BIAS))[tid] = b_ih[n0 + tid] + b_hh[n0 + tid];
    }

    unsigned phase = 0;
    if (tid == 0) phase = ((volatile unsigned*)&g_bar_phase4[ctaM * 32])[0];
    __syncthreads();

    // Per-lane fragment address constants (byte-isomorphic to proven bf16 path)
    const int arow = (lid & 7) + ((lid >> 3) & 1) * 8;
    const int aka2 = ((lid >> 4) & 1) * 16;
    const int axor = (arow & 7) * 16;
    const uint32_t stage_base = smb + SM_ASTAGE + (uint32_t)stream * 16384;
    const uint32_t a_lane = stage_base + (uint32_t)(wm * 16 + arow) * 128;

    const int brow = wn * 16 + (lid & 7) + ((lid >> 4) & 1) * 8;
    const int bka2 = ((lid >> 3) & 1) * 16;
    const int bxor = (brow & 7) * 16;
    const uint32_t bhh_lane = smb + SM_W1 + (uint32_t)brow * 1024;   // plane0 at +32768
    const uint32_t bih_lane = smb + SM_WI1 + (uint32_t)brow * 256;   // plane0 at +8192

    const int g  = lid >> 2;
    const int tg = lid & 3;

    for (int t = 0; t < T_; t++) {
        const char* h1p = g_h1[t & 1];
        const char* h0p = g_h0[t & 1];

        int acc_hi[2][4], acc_mid[2][4], acc_xhi[2][4], acc_xmid[2][4];
        #pragma unroll
        for (int n = 0; n < 2; n++)
            #pragma unroll
            for (int j = 0; j < 4; j++) {
                acc_hi[n][j] = 0; acc_mid[n][j] = 0;
                acc_xhi[n][j] = 0; acc_xmid[n][j] = 0;
            }

        // Stream s: chunks {s, s+2, s+4, s+6 (h), 8+s (x)}, 2 stages of 8KB.
        load_chunk(stage_base, stream, h1p, h0p, m0, t, stid);
        asm volatile("cp.async.commit_group;");

        #pragma unroll
        for (int i = 0; i < 5; i++) {
            asm volatile("cp.async.wait_group 0;");   // chunk i data in
            stream_bar(stream);   // visible to all stream warps; chunk i-1 done
            const int c = 2 * i + stream;
            if (i < 4) {
                load_chunk(stage_base + (uint32_t)((i + 1) & 1) * 8192,
                           c + 2, h1p, h0p, m0, t, stid);
                asm volatile("cp.async.commit_group;");
            }

            const uint32_t a_base = a_lane + (uint32_t)(i & 1) * 8192;

            if (i < 4) {   // h chunk: accumulate into acc_hi/acc_mid (scale 2^32)
                const int kb0 = c * 128;
                #pragma unroll
                for (int kk = 0; kk < 4; kk++) {
                    uint32_t a1v[4], a0v[4], b1v[4], b0v[4];
                    uint32_t ao = (uint32_t)((kk * 32 + aka2) ^ axor);
                    ldsm_x4(a1v, a_base + ao);
                    ldsm_x4(a0v, a_base + 4096 + ao);
                    uint32_t bo = (uint32_t)((kb0 + kk * 32 + bka2) ^ bxor);
                    ldsm_x4(b1v, bhh_lane + bo);
                    ldsm_x4(b0v, bhh_lane + 32768 + bo);

                    imma16832(acc_hi[0],  a1v, b1v[0], b1v[1]);
                    imma16832(acc_mid[0], a1v, b0v[0], b0v[1]);
                    imma16832(acc_mid[0], a0v, b1v[0], b1v[1]);
                    imma16832(acc_hi[1],  a1v, b1v[2], b1v[3]);
                    imma16832(acc_mid[1], a1v, b0v[2], b0v[3]);
                    imma16832(acc_mid[1], a0v, b1v[2], b1v[3]);
                }
            } else {       // x chunk: accumulate into acc_xhi/acc_xmid (scale 2^29)
                const int kb0 = stream * 128;
                #pragma unroll
                for (int kk = 0; kk < 4; kk++) {
                    uint32_t a1v[4], a0v[4], b1v[4], b0v[4];
                    uint32_t ao = (uint32_t)((kk * 32 + aka2) ^ axor);
                    ldsm_x4(a1v, a_base + ao);
                    ldsm_x4(a0v, a_base + 4096 + ao);
                    uint32_t bo = (uint32_t)((kb0 + kk * 32 + bka2) ^ bxor);
                    ldsm_x4(b1v, bih_lane + bo);
                    ldsm_x4(b0v, bih_lane + 8192 + bo);

                    imma16832(acc_xhi[0],  a1v, b1v[0], b1v[1]);
                    imma16832(acc_xmid[0], a1v, b0v[0], b0v[1]);
                    imma16832(acc_xmid[0], a0v, b1v[0], b1v[1]);
                    imma16832(acc_xhi[1],  a1v, b1v[2], b1v[3]);
                    imma16832(acc_xmid[1], a1v, b0v[2], b0v[3]);
                    imma16832(acc_xmid[1], a0v, b1v[2], b1v[3]);
                }
            }
        }
        stream_bar(stream);   // all stream warps done with stages

        // ---- Epilogue: exact scale-combine, merge streams, tanh, plane split ----
        {
            const float INV32 = 2.3283064365386963e-10f;  // 2^-32 (h*Whh)
            const float INV29 = 1.862645149230957e-09f;   // 2^-29 (x*Wih)
            float vs[2][4];
            #pragma unroll
            for (int nt = 0; nt < 2; nt++)
                #pragma unroll
                for (int j = 0; j < 4; j++)
                    vs[nt][j] =
                        ((float)acc_hi[nt][j] * 16384.f + (float)acc_mid[nt][j] * 128.f) * INV32 +
                        ((float)acc_xhi[nt][j] * 16384.f + (float)acc_xmid[nt][j] * 128.f) * INV29;

            float* red = (float*)(sm + SM_RED);   // stream1 stage0 (idle now)
            if (stream == 1) {
                #pragma unroll
                for (int nt = 0; nt < 2; nt++) {
                    int nloc = wn * 16 + nt * 8 + tg * 2;
                    #pragma unroll
                    for (int rp = 0; rp < 2; rp++) {
                        int mloc = wm * 16 + g + rp * 8;
                        red[mloc * 32 + nloc]     = vs[nt][rp * 2 + 0];
                        red[mloc * 32 + nloc + 1] = vs[nt][rp * 2 + 1];
                    }
                }
            }
            __syncthreads();
            if (stream == 0) {
                char* __restrict__ oh1 = g_h1[(t + 1) & 1];
                char* __restrict__ oh0 = g_h0[(t + 1) & 1];
                const float* bias = (const float*)(sm + SM_BIAS);
                const bool last = (t == T_ - 1);
                #pragma unroll
                for (int nt = 0; nt < 2; nt++) {
                    int nloc = wn * 16 + nt * 8 + tg * 2;
                    int ng = n0 + nloc;
                    float b0v = bias[nloc], b1v = bias[nloc + 1];
                    #pragma unroll
                    for (int rp = 0; rp < 2; rp++) {
                        int mloc = wm * 16 + g + rp * 8;
                        int mg = m0 + mloc;
                        float v0 = tanhf(vs[nt][rp * 2 + 0] + red[mloc * 32 + nloc] + b0v);
                        float v1 = tanhf(vs[nt][rp * 2 + 1] + red[mloc * 32 + nloc + 1] + b1v);
                        int Ha = __float2int_rn(v0 * 16384.f);
                        int Hb = __float2int_rn(v1 * 16384.f);
                        Ha = max(min(Ha, 16319), -16320);
                        Hb = max(min(Hb, 16319), -16320);
                        int p1a = (Ha + 64) >> 7, p0a = Ha - (p1a << 7);
                        int p1b = (Hb + 64) >> 7, p0b = Hb - (p1b << 7);
                        size_t idx = (size_t)mg * H_ + ng;
                        *(uint16_t*)(oh1 + idx) =
                            (uint16_t)((p1a & 0xFF) | ((p1b & 0xFF) << 8));
                        *(uint16_t*)(oh0 + idx) =
                            (uint16_t)((p0a & 0xFF) | ((p0b & 0xFF) << 8));
                        if (last) {
                            float2 f2v; f2v.x = v0; f2v.y = v1;
                            *(float2*)(g_h32 + idx) = f2v;
                        }
                    }
                }
            }
        }

        __threadfence();   // h stores visible GPU-wide before barrier release
        group_barrier(ctaM, &phase);
    }
}

// ---------------------------------------------------------------------------
// fc epilogue: one block per batch; warp-per-output-column, lanes split K.
// ---------------------------------------------------------------------------
__global__ __launch_bounds__(256) void fc_kernel(
    const float* __restrict__ W_fc, const float* __restrict__ b_fc,
    float* __restrict__ out)
{
    __shared__ float4 hsv4[H_ / 4];
    const int b = blockIdx.x;
    const int tid = threadIdx.x;
    const int wid = tid >> 5;
    const int lid = tid & 31;

    hsv4[tid] = ((const float4*)(g_h32 + (size_t)b * H_))[tid];
    __syncthreads();

    #pragma unroll 4
    for (int oi = 0; oi < 32; oi++) {
        const int o = wid * 32 + oi;
        const float4* __restrict__ w4 = (const float4*)(W_fc + (size_t)o * H_);
        float a0 = 0.f, a1 = 0.f;
        #pragma unroll
        for (int i = 0; i < 8; i++) {
            float4 w = w4[lid + i * 32];
            float4 h = hsv4[lid + i * 32];
            if (i & 1) a1 += w.x * h.x + w.y * h.y + w.z * h.z + w.w * h.w;
            else       a0 += w.x * h.x + w.y * h.y + w.z * h.z + w.w * h.w;
        }
        float acc = a0 + a1;
        #pragma unroll
        for (int off = 16; off > 0; off >>= 1)
            acc += __shfl_xor_sync(0xFFFFFFFFu, acc, off);
        if (lid == 0) out[(size_t)b * O_ + o] = acc + b_fc[o];
    }
}

__global__ void copy_hidden(float* __restrict__ dst)
{
    int idx = blockIdx.x * blockDim.x + threadIdx.x;
    if (idx < B_ * H_) dst[idx] = g_h32[idx];
}

// ---------------------------------------------------------------------------
extern "C" void kernel_launch(void* const* d_in, const int* in_sizes, int n_in,
                              void* d_out, int out_size)
{
    const float* x      = (const float*)d_in[0];
    const float* hidden = (const float*)d_in[1];
    const float* W_ih   = (const float*)d_in[2];
    const float* W_hh   = (const float*)d_in[3];
    const float* b_ih   = (const float*)d_in[4];
    const float* b_hh   = (const float*)d_in[5];
    const float* W_fc   = (const float*)d_in[6];
    const float* b_fc   = (const float*)d_in[7];
    float* out = (float*)d_out;

    cudaFuncSetAttribute(rnn_persistent, cudaFuncAttributeMaxDynamicSharedMemorySize,
                         SM_TOTAL);

    // 1) split x and initial hidden into int8 planes
    split_x_int8<<<(B_ * T_ * I_ + 255) / 256, 256>>>(x);
    init_h_int8<<<(B_ * H_ + 255) / 256, 256>>>(hidden);

    // 2) full recurrence in ONE persistent launch (IMMA s8, 2x fewer tensor ops)
    rnn_persistent<<<NB, NTHR, SM_TOTAL>>>(b_ih, b_hh, W_hh, W_ih);

    // 3) fc epilogue + hidden output
    fc_kernel<<<B_, 256>>>(W_fc, b_fc, out);
    if (out_size >= B_ * O_ + B_ * H_)
        copy_hidden<<<(B_ * H_ + 255) / 256, 256>>>(out + B_ * O_);
}

// round 17
// speedup vs baseline: 1.6728x; 1.6728x over previous
#include <cuda_runtime.h>
#include <cuda_bf16.h>
#include <math.h>
#include <stdint.h>

// Problem constants
#define B_ 128
#define T_ 512
#define I_ 256
#define H_ 1024
#define O_ 256

#define NB   128      // persistent grid: 4 M-tiles x 32 N-tiles
#define NTHR 256      // 8 warps: warps 0-3 = stream 0 (even chunks), 4-7 = stream 1

// ---------------------------------------------------------------------------
// Device-global scratch (allocation-free per harness rules)
// ---------------------------------------------------------------------------
__device__ __nv_bfloat16 g_x_hi[(size_t)B_ * T_ * I_];
__device__ __nv_bfloat16 g_x_lo[(size_t)B_ * T_ * I_];
__device__ __nv_bfloat16 g_h_hi[2][B_ * H_];
__device__ __nv_bfloat16 g_h_lo[2][B_ * H_];
__device__ float g_h32[B_ * H_];
// Group-local barriers: batch-group g uses slot g*32 (128B padding)
__device__ unsigned g_bar_count4[128];
__device__ unsigned g_bar_phase4[128];

// ---------------------------------------------------------------------------
// SMEM layout (identical to the proven 3267us version)
// ---------------------------------------------------------------------------
#define SM_WHH_HI 0            // 32 rows x 2048B, swizzled (col XOR row)
#define SM_WHH_LO 65536
#define SM_WIH_HI 131072       // 32 rows x 512B, swizzled (col XOR row)
#define SM_WIH_LO 147456
#define SM_ASTAGE 163840       // per stream: 2 stages x 16KB; stream1 at +32768
#define SM_RED    (SM_ASTAGE + 32768)   // reduction buffer: stream1 stage 0
#define SM_BIAS   229376       // 32 floats
#define SM_TOTAL  229632

// ---------------------------------------------------------------------------
// PTX helpers (portable ISA for plain sm_103 target — NO tcgen05)
// ---------------------------------------------------------------------------
__device__ __forceinline__ uint32_t smem_u32(const void* p) {
    uint32_t a;
    asm("{ .reg .u64 t; cvta.to.shared.u64 t, %1; cvt.u32.u64 %0, t; }" : "=r"(a) : "l"(p));
    return a;
}

__device__ __forceinline__ void cp16(uint32_t saddr, const void* gptr) {
    asm volatile("cp.async.cg.shared.global [%0], [%1], 16;"
                 :: "r"(saddr), "l"(__cvta_generic_to_global(gptr)));
}

__device__ __forceinline__ void ldsm_x4(uint32_t* r, uint32_t addr) {
    asm volatile("ldmatrix.sync.aligned.m8n8.x4.shared.b16 {%0,%1,%2,%3}, [%4];"
                 : "=r"(r[0]), "=r"(r[1]), "=r"(r[2]), "=r"(r[3]) : "r"(addr));
}

__device__ __forceinline__ void mma16816(float* c, const uint32_t* a, uint32_t b0, uint32_t b1) {
    asm volatile(
        "mma.sync.aligned.m16n8k16.row.col.f32.bf16.bf16.f32 "
        "{%0,%1,%2,%3}, {%4,%5,%6,%7}, {%8,%9}, {%0,%1,%2,%3};"
        : "+f"(c[0]), "+f"(c[1]), "+f"(c[2]), "+f"(c[3])
        : "r"(a[0]), "r"(a[1]), "r"(a[2]), "r"(a[3]), "r"(b0), "r"(b1));
}

// Exact-identity fast tanh: tanh(x) = 1 - 2/(e^{2x}+1).
// Only error sources are ex2.approx (~2ulp) and rcp.approx (~1ulp):
// absolute error ~2e-7, below the bf16-split per-step noise. Saturation exact.
__device__ __forceinline__ float fast_tanh(float x) {
    float e;
    asm("ex2.approx.f32 %0, %1;" : "=f"(e) : "f"(x * 2.8853900817779268f)); // 2*log2(e)
    float r;
    asm("rcp.approx.f32 %0, %1;" : "=f"(r) : "f"(e + 1.0f));
    return 1.0f - 2.0f * r;
}

__device__ __forceinline__ void stream_bar(int stream) {
    asm volatile("bar.sync %0, 128;" :: "r"(1 + stream) : "memory");
}

// Group-local sense-reversing barrier: 32 CTAs sharing a batch group (ctaM)
__device__ __forceinline__ void group_barrier(int grp, unsigned* phase) {
    __syncthreads();
    if (threadIdx.x == 0) {
        unsigned target = *phase + 1;
        unsigned* cnt = &g_bar_count4[grp * 32];
        unsigned* ph  = &g_bar_phase4[grp * 32];
        if (atomicAdd(cnt, 1) == 31) {
            *cnt = 0;
            __threadfence();
            atomicExch(ph, target);
        } else {
            while (((volatile unsigned*)ph)[0] != target) {}
            __threadfence();
        }
        *phase = target;
    }
    __syncthreads();
}

// ---------------------------------------------------------------------------
// Split prep kernel (x and initial hidden; W splits happen in prologue)
// ---------------------------------------------------------------------------
__global__ void split_pair(const float* __restrict__ src,
                           __nv_bfloat16* __restrict__ hi,
                           __nv_bfloat16* __restrict__ lo, int n)
{
    int i = blockIdx.x * blockDim.x + threadIdx.x;
    if (i < n) {
        float v = src[i];
        __nv_bfloat16 h = __float2bfloat16(v);
        hi[i] = h;
        lo[i] = __float2bfloat16(v - __bfloat162float(h));
    }
}

// ---------------------------------------------------------------------------
// Stream-local chunk loader: 128 threads load 16KB (hi 8KB + lo 8KB).
// Swizzle: column offset XOR ((row&7)*16). c<8: h slice; c>=8: x_t slice.
// ---------------------------------------------------------------------------
__device__ __forceinline__ void load_chunk(uint32_t sstage, int c,
    const char* __restrict__ hhi, const char* __restrict__ hlo,
    int m0, int t, int stid)
{
    if (c < 8) {
        #pragma unroll
        for (int i = 0; i < 4; i++) {
            int u = stid + i * 128;
            int row = u >> 4, uk = u & 15;
            int so = row * 256 + ((uk * 16) ^ ((row & 7) * 16));
            size_t go = (size_t)(m0 + row) * 2048 + (size_t)c * 256 + uk * 16;
            cp16(sstage + so, hhi + go);
            cp16(sstage + 8192 + so, hlo + go);
        }
    } else {
        int cx = c - 8;
        #pragma unroll
        for (int i = 0; i < 4; i++) {
            int u = stid + i * 128;
            int row = u >> 4, uk = u & 15;
            int so = row * 256 + ((uk * 16) ^ ((row & 7) * 16));
            size_t go = ((size_t)(m0 + row) * T_ + t) * 512 + (size_t)cx * 256 + uk * 16;
            cp16(sstage + so, (const char*)g_x_hi + go);
            cp16(sstage + 8192 + so, (const char*)g_x_lo + go);
        }
    }
}

// ---------------------------------------------------------------------------
// Persistent recurrence: 512 steps, one launch (proven 3267us structure).
// CTA (ctaM, ctaN): M-tile 32 batches, N-tile 32 cols, K = 1024(h)+256(x).
// Dual K-parity streams of 4 warps (M16xN16 warp tiles).
// ---------------------------------------------------------------------------
__global__ __launch_bounds__(NTHR, 1) void rnn_persistent(
    const float* __restrict__ b_ih, const float* __restrict__ b_hh,
    const float* __restrict__ Whh, const float* __restrict__ Wih,
    float* __restrict__ hid_out)
{
    extern __shared__ char sm[];
    const uint32_t smb = smem_u32(sm);
    const int tid = threadIdx.x;
    const int lid = tid & 31;
    const int wid = tid >> 5;
    const int stream = wid >> 2;
    const int stid = tid & 127;
    const int swid = wid & 3;
    const int wm = swid >> 1, wn = swid & 1;
    const int ctaM = blockIdx.x >> 5;
    const int ctaN = blockIdx.x & 31;
    const int m0 = ctaM * 32;
    const int n0 = ctaN * 32;

    // ---- Prologue: split W slices fp32 -> bf16 hi/lo directly into smem.
    // Store swizzle matches ldmatrix read path: (col16B) ^ ((row&7)*16).
    {
        for (int u = tid; u < 8192; u += NTHR) {
            int row = u >> 8, k4 = u & 255;
            float4 v = *(const float4*)(Whh + (size_t)(n0 + row) * H_ + k4 * 4);
            __nv_bfloat162 h01 = __floats2bfloat162_rn(v.x, v.y);
            __nv_bfloat162 h23 = __floats2bfloat162_rn(v.z, v.w);
            __nv_bfloat162 l01 = __floats2bfloat162_rn(
                v.x - __bfloat162float(h01.x), v.y - __bfloat162float(h01.y));
            __nv_bfloat162 l23 = __floats2bfloat162_rn(
                v.z - __bfloat162float(h23.x), v.w - __bfloat162float(h23.y));
            int so = row * 2048 + ((k4 * 8) ^ ((row & 7) * 16));
            uint2 hp; hp.x = *(uint32_t*)&h01; hp.y = *(uint32_t*)&h23;
            uint2 lp; lp.x = *(uint32_t*)&l01; lp.y = *(uint32_t*)&l23;
            *(uint2*)(sm + SM_WHH_HI + so) = hp;
            *(uint2*)(sm + SM_WHH_LO + so) = lp;
        }
        for (int u = tid; u < 2048; u += NTHR) {
            int row = u >> 6, k4 = u & 63;
            float4 v = *(const float4*)(Wih + (size_t)(n0 + row) * I_ + k4 * 4);
            __nv_bfloat162 h01 = __floats2bfloat162_rn(v.x, v.y);
            __nv_bfloat162 h23 = __floats2bfloat162_rn(v.z, v.w);
            __nv_bfloat162 l01 = __floats2bfloat162_rn(
                v.x - __bfloat162float(h01.x), v.y - __bfloat162float(h01.y));
            __nv_bfloat162 l23 = __floats2bfloat162_rn(
                v.z - __bfloat162float(h23.x), v.w - __bfloat162float(h23.y));
            int so = row * 512 + ((k4 * 8) ^ ((row & 7) * 16));
            uint2 hp; hp.x = *(uint32_t*)&h01; hp.y = *(uint32_t*)&h23;
            uint2 lp; lp.x = *(uint32_t*)&l01; lp.y = *(uint32_t*)&l23;
            *(uint2*)(sm + SM_WIH_HI + so) = hp;
            *(uint2*)(sm + SM_WIH_LO + so) = lp;
        }
        if (tid < 32)
            ((float*)(sm + SM_BIAS))[tid] = b_ih[n0 + tid] + b_hh[n0 + tid];
    }

    unsigned phase = 0;
    if (tid == 0) phase = ((volatile unsigned*)&g_bar_phase4[ctaM * 32])[0];
    __syncthreads();

    // Per-lane fragment address constants (proven in R7/R10)
    const int arow = (lid & 7) + ((lid >> 3) & 1) * 8;
    const int aka2 = ((lid >> 4) & 1) * 16;
    const int axor = (arow & 7) * 16;
    const uint32_t stage_base = smb + SM_ASTAGE + (uint32_t)stream * 32768;
    const uint32_t a_lane = stage_base + (uint32_t)(wm * 16 + arow) * 256;

    const int brow = wn * 16 + (lid & 7) + ((lid >> 4) & 1) * 8;
    const int bka2 = ((lid >> 3) & 1) * 16;
    const int bxor = (brow & 7) * 16;
    const uint32_t bhh_lane = smb + SM_WHH_HI + (uint32_t)brow * 2048;
    const uint32_t bih_lane = smb + SM_WIH_HI + (uint32_t)brow * 512;

    const int g  = lid >> 2;
    const int tg = lid & 3;

    for (int t = 0; t < T_; t++) {
        const char* hhi = (const char*)g_h_hi[t & 1];
        const char* hlo = (const char*)g_h_lo[t & 1];

        float acc[2][2][4];
        #pragma unroll
        for (int p = 0; p < 2; p++)
            #pragma unroll
            for (int n = 0; n < 2; n++)
                #pragma unroll
                for (int j = 0; j < 4; j++) acc[p][n][j] = 0.f;

        // Stream s handles chunks {s, s+2, ..., s+8} (5 chunks), 2 private stages.
        load_chunk(stage_base, stream, hhi, hlo, m0, t, stid);
        asm volatile("cp.async.commit_group;");

        #pragma unroll
        for (int i = 0; i < 5; i++) {
            asm volatile("cp.async.wait_group 0;");   // chunk i data in
            stream_bar(stream);   // data visible; all stream warps done mma(i-1)
            const int c = 2 * i + stream;
            if (i < 4) {          // prefetch next chunk into the now-free stage
                load_chunk(stage_base + (uint32_t)((i + 1) & 1) * 16384,
                           c + 2, hhi, hlo, m0, t, stid);
                asm volatile("cp.async.commit_group;");
            }

            const uint32_t a_base = a_lane + (uint32_t)(i & 1) * 16384;
            uint32_t b_base, b_dlo;
            int kb0;
            if (c < 8) { b_base = bhh_lane; b_dlo = 65536; kb0 = c * 256; }
            else       { b_base = bih_lane; b_dlo = 16384; kb0 = (c - 8) * 256; }

            #pragma unroll
            for (int kk = 0; kk < 8; kk++) {
                uint32_t ahi[4], alo[4], bh[4], bl[4];
                uint32_t ao = (uint32_t)((kk * 32 + aka2) ^ axor);
                ldsm_x4(ahi, a_base + ao);
                ldsm_x4(alo, a_base + 8192 + ao);
                uint32_t bo = (uint32_t)((kb0 + kk * 32 + bka2) ^ bxor);
                ldsm_x4(bh, b_base + bo);          // NON-trans: [n][k] row-major
                ldsm_x4(bl, b_base + b_dlo + bo);

                float* C0 = acc[kk & 1][0];
                float* C1 = acc[kk & 1][1];
                mma16816(C0, ahi, bh[0], bh[1]);   // Ahi*Bhi
                mma16816(C1, ahi, bh[2], bh[3]);
                mma16816(C0, ahi, bl[0], bl[1]);   // Ahi*Blo
                mma16816(C1, ahi, bl[2], bl[3]);
                mma16816(C0, alo, bh[0], bh[1]);   // Alo*Bhi
                mma16816(C1, alo, bh[2], bh[3]);
            }
        }
        stream_bar(stream);   // all stream warps done with stages before red reuse

        // ---- Epilogue: merge streams, +bias, fast tanh, split-bf16 store ----
        {
            float vs[2][4];
            #pragma unroll
            for (int nt = 0; nt < 2; nt++)
                #pragma unroll
                for (int j = 0; j < 4; j++)
                    vs[nt][j] = acc[0][nt][j] + acc[1][nt][j];

            float* red = (float*)(sm + SM_RED);   // stream1 stage area (now idle)
            if (stream == 1) {
                #pragma unroll
                for (int nt = 0; nt < 2; nt++) {
                    int nloc = wn * 16 + nt * 8 + tg * 2;
                    #pragma unroll
                    for (int rp = 0; rp < 2; rp++) {
                        int mloc = wm * 16 + g + rp * 8;
                        red[mloc * 32 + nloc]     = vs[nt][rp * 2 + 0];
                        red[mloc * 32 + nloc + 1] = vs[nt][rp * 2 + 1];
                    }
                }
            }
            __syncthreads();
            if (stream == 0) {
                __nv_bfloat16* __restrict__ ohi = g_h_hi[(t + 1) & 1];
                __nv_bfloat16* __restrict__ olo = g_h_lo[(t + 1) & 1];
                const float* bias = (const float*)(sm + SM_BIAS);
                const bool last = (t == T_ - 1);
                #pragma unroll
                for (int nt = 0; nt < 2; nt++) {
                    int nloc = wn * 16 + nt * 8 + tg * 2;
                    int ng = n0 + nloc;
                    float b0v = bias[nloc], b1v = bias[nloc + 1];
                    #pragma unroll
                    for (int rp = 0; rp < 2; rp++) {
                        int mloc = wm * 16 + g + rp * 8;
                        int mg = m0 + mloc;
                        float v0 = fast_tanh(vs[nt][rp * 2 + 0] + red[mloc * 32 + nloc] + b0v);
                        float v1 = fast_tanh(vs[nt][rp * 2 + 1] + red[mloc * 32 + nloc + 1] + b1v);
                        __nv_bfloat16 h0 = __float2bfloat16(v0);
                        __nv_bfloat16 h1 = __float2bfloat16(v1);
                        __nv_bfloat16 l0 = __float2bfloat16(v0 - __bfloat162float(h0));
                        __nv_bfloat16 l1 = __float2bfloat16(v1 - __bfloat162float(h1));
                        size_t idx = (size_t)mg * H_ + ng;
                        *(uint32_t*)(ohi + idx) =
                            ((uint32_t)*(uint16_t*)&h1 << 16) | *(uint16_t*)&h0;
                        *(uint32_t*)(olo + idx) =
                            ((uint32_t)*(uint16_t*)&l1 << 16) | *(uint16_t*)&l0;
                        if (last) {
                            float2 f2v; f2v.x = v0; f2v.y = v1;
                            *(float2*)(g_h32 + idx) = f2v;
                            if (hid_out) *(float2*)(hid_out + idx) = f2v;
                        }
                    }
                }
            }
        }

        __threadfence();   // h stores visible GPU-wide before barrier release
        group_barrier(ctaM, &phase);
    }
}

// ---------------------------------------------------------------------------
// fc epilogue: one block per batch; warp-per-output-column, lanes split K.
// ---------------------------------------------------------------------------
__global__ __launch_bounds__(256) void fc_kernel(
    const float* __restrict__ W_fc, const float* __restrict__ b_fc,
    float* __restrict__ out)
{
    __shared__ float4 hsv4[H_ / 4];
    const int b = blockIdx.x;
    const int tid = threadIdx.x;
    const int wid = tid >> 5;
    const int lid = tid & 31;

    hsv4[tid] = ((const float4*)(g_h32 + (size_t)b * H_))[tid];
    __syncthreads();

    #pragma unroll 4
    for (int oi = 0; oi < 32; oi++) {
        const int o = wid * 32 + oi;
        const float4* __restrict__ w4 = (const float4*)(W_fc + (size_t)o * H_);
        float a0 = 0.f, a1 = 0.f;
        #pragma unroll
        for (int i = 0; i < 8; i++) {
            float4 w = w4[lid + i * 32];
            float4 h = hsv4[lid + i * 32];
            if (i & 1) a1 += w.x * h.x + w.y * h.y + w.z * h.z + w.w * h.w;
            else       a0 += w.x * h.x + w.y * h.y + w.z * h.z + w.w * h.w;
        }
        float acc = a0 + a1;
        #pragma unroll
        for (int off = 16; off > 0; off >>= 1)
            acc += __shfl_xor_sync(0xFFFFFFFFu, acc, off);
        if (lid == 0) out[(size_t)b * O_ + o] = acc + b_fc[o];
    }
}

// ---------------------------------------------------------------------------
extern "C" void kernel_launch(void* const* d_in, const int* in_sizes, int n_in,
                              void* d_out, int out_size)
{
    const float* x      = (const float*)d_in[0];
    const float* hidden = (const float*)d_in[1];
    const float* W_ih   = (const float*)d_in[2];
    const float* W_hh   = (const float*)d_in[3];
    const float* b_ih   = (const float*)d_in[4];
    const float* b_hh   = (const float*)d_in[5];
    const float* W_fc   = (const float*)d_in[6];
    const float* b_fc   = (const float*)d_in[7];
    float* out = (float*)d_out;

    cudaFuncSetAttribute(rnn_persistent, cudaFuncAttributeMaxDynamicSharedMemorySize,
                         SM_TOTAL);

    static __nv_bfloat16 *p_xhi = nullptr, *p_xlo = nullptr,
                         *p_hhi = nullptr, *p_hlo = nullptr;
    if (!p_xhi) {
        cudaGetSymbolAddress((void**)&p_xhi, g_x_hi);
        cudaGetSymbolAddress((void**)&p_xlo, g_x_lo);
        cudaGetSymbolAddress((void**)&p_hhi, g_h_hi);
        cudaGetSymbolAddress((void**)&p_hlo, g_h_lo);
    }

    // 1) split x and initial hidden to bf16 hi/lo (W splits live in prologue)
    split_pair<<<(B_ * T_ * I_ + 255) / 256, 256>>>(x, p_xhi, p_xlo, B_ * T_ * I_);
    split_pair<<<(B_ * H_ + 255) / 256, 256>>>(hidden, p_hhi, p_hlo, B_ * H_);

    // 2) full recurrence in ONE persistent launch; writes hidden output directly
    float* hid_out = (out_size >= B_ * O_ + B_ * H_) ? (out + B_ * O_) : nullptr;
    rnn_persistent<<<NB, NTHR, SM_TOTAL>>>(b_ih, b_hh, W_hh, W_ih, hid_out);

    // 3) fc epilogue
    fc_kernel<<<B_, 256>>>(W_fc, b_fc, out);
}